// round 2
// baseline (speedup 1.0000x reference)
#include <cuda_runtime.h>
#include <cuda_bf16.h>

// Problem: M=3, L=16, BATCH=2e6.
// y[b] = sum_{s=0}^{21} w[s] * r_s, r_s = value of largest-m valid candidate
// (l = s-3m in [0,15]) with cond true; val = 0.5*cos(x_m - phi_{m,l}) + 0.5.
// cond = (d > -iv_m) && (d <= iv_m), d = x_m - phi_{m,l}  (computed EXACTLY as ref).
// val only selected when |d| <= iv <= 1  ->  degree-6 even Taylor of 0.5+0.5cos(d),
// max abs error 1.22e-5 on [-1,1]  (way under the 1e-3 threshold).
// Output: d_out[0..B) = y, d_out[B..B+48) = weight echo.

#define M_DIM 3
#define L_DIM 16
#define NSEG 22

typedef unsigned long long u64p;  // packed f32x2 carrier

__device__ __forceinline__ u64p pk2(float lo, float hi) {
    u64p r; asm("mov.b64 %0, {%1, %2};" : "=l"(r) : "f"(lo), "f"(hi)); return r;
}
__device__ __forceinline__ void upk2(u64p v, float& lo, float& hi) {
    asm("mov.b64 {%0, %1}, %2;" : "=f"(lo), "=f"(hi) : "l"(v));
}
__device__ __forceinline__ u64p add2(u64p a, u64p b) {
    u64p r; asm("add.rn.f32x2 %0, %1, %2;" : "=l"(r) : "l"(a), "l"(b)); return r;
}
__device__ __forceinline__ u64p mul2(u64p a, u64p b) {
    u64p r; asm("mul.rn.f32x2 %0, %1, %2;" : "=l"(r) : "l"(a), "l"(b)); return r;
}
__device__ __forceinline__ u64p fma2(u64p a, u64p b, u64p c) {
    u64p r; asm("fma.rn.f32x2 %0, %1, %2, %3;" : "=l"(r) : "l"(a), "l"(b), "l"(c)); return r;
}

// Precomputed: duplicated (-phi,-phi) per entry; per-m interval bounds.
__device__ u64p  g_nphi2[M_DIM * L_DIM];
__device__ float g_niv[M_DIM];
__device__ float g_piv[M_DIM];

__global__ void setup_kernel(const float* __restrict__ phis,
                             const float* __restrict__ interval) {
    int e = threadIdx.x;
    if (e < M_DIM * L_DIM) {
        float np = -phis[e];
        g_nphi2[e] = pk2(np, np);
    }
    if (e < M_DIM) {
        float iv = interval[e];
        g_niv[e] = -iv;
        g_piv[e] = iv;
    }
}

// Taylor of 0.5 + 0.5*cos(d) in u = d*d
#define C1_COEF (-0.25f)
#define C2_COEF (2.0833333333e-2f)   //  1/48
#define C3_COEF (-6.9444444444e-4f)  // -1/1440

__global__ void __launch_bounds__(256)
main_kernel(const float* __restrict__ x,
            const float* __restrict__ w,
            float* __restrict__ out,
            int B) {
    __shared__ u64p  sP[M_DIM * L_DIM];
    __shared__ float sW[NSEG];
    __shared__ float sNiv[M_DIM];
    __shared__ float sPiv[M_DIM];

    int t = threadIdx.x;
    if (t < M_DIM * L_DIM) sP[t] = g_nphi2[t];
    if (t < NSEG)          sW[t] = w[t];
    if (t < M_DIM) { sNiv[t] = g_niv[t]; sPiv[t] = g_piv[t]; }
    __syncthreads();

    long long g = (long long)blockIdx.x * blockDim.x + t;
    long long base = 4 * g;
    if (base >= B) return;

    // interval bounds in registers
    float niv[M_DIM], piv[M_DIM];
    #pragma unroll
    for (int m = 0; m < M_DIM; m++) { niv[m] = sNiv[m]; piv[m] = sPiv[m]; }

    const u64p C1p  = pk2(C1_COEF, C1_COEF);
    const u64p C2p  = pk2(C2_COEF, C2_COEF);
    const u64p C3p  = pk2(C3_COEF, C3_COEF);
    const u64p ONEp = pk2(1.0f, 1.0f);

    if (base + 3 < B) {
        // Fast path: 4 elements, 12 consecutive floats = 3 aligned float4s
        const float4* x4 = (const float4*)x;
        float4 a = x4[3 * g + 0];
        float4 b = x4[3 * g + 1];
        float4 c = x4[3 * g + 2];
        // element e, component m lives at float index 3e+m
        // pairs: pair0 = (elem0, elem1), pair1 = (elem2, elem3)
        u64p xm[M_DIM][2];
        xm[0][0] = pk2(a.x, a.w);  xm[0][1] = pk2(b.z, c.y);
        xm[1][0] = pk2(a.y, b.x);  xm[1][1] = pk2(b.w, c.z);
        xm[2][0] = pk2(a.z, b.y);  xm[2][1] = pk2(c.x, c.w);

        float acc0 = 0.0f, acc1 = 0.0f, acc2 = 0.0f, acc3 = 0.0f;

        #pragma unroll
        for (int s = 0; s < NSEG; s++) {
            float r0 = 0.0f, r1 = 0.0f, r2 = 0.0f, r3 = 0.0f;
            #pragma unroll
            for (int m = 0; m < M_DIM; m++) {
                const int l = s - 3 * m;
                if (l < 0 || l >= L_DIM) continue;
                u64p ph = sP[m * L_DIM + l];
                // d = x - phi  (exact: x + (-phi))
                u64p dA = add2(xm[m][0], ph);
                u64p dB = add2(xm[m][1], ph);
                u64p uA = mul2(dA, dA);
                u64p uB = mul2(dB, dB);
                // val = 1 + u*(C1 + u*(C2 + u*C3))
                u64p tA = fma2(uA, C3p, C2p);
                u64p tB = fma2(uB, C3p, C2p);
                tA = fma2(tA, uA, C1p);
                tB = fma2(tB, uB, C1p);
                u64p vA = fma2(tA, uA, ONEp);
                u64p vB = fma2(tB, uB, ONEp);
                float d0, d1, d2, d3, v0, v1, v2, v3;
                upk2(dA, d0, d1); upk2(dB, d2, d3);
                upk2(vA, v0, v1); upk2(vB, v2, v3);
                // cond computed exactly as reference
                bool c0 = (d0 > niv[m]) && (d0 <= piv[m]);
                bool c1 = (d1 > niv[m]) && (d1 <= piv[m]);
                bool c2 = (d2 > niv[m]) && (d2 <= piv[m]);
                bool c3 = (d3 > niv[m]) && (d3 <= piv[m]);
                r0 = c0 ? v0 : r0;
                r1 = c1 ? v1 : r1;
                r2 = c2 ? v2 : r2;
                r3 = c3 ? v3 : r3;
            }
            float ws = sW[s];
            acc0 = fmaf(ws, r0, acc0);
            acc1 = fmaf(ws, r1, acc1);
            acc2 = fmaf(ws, r2, acc2);
            acc3 = fmaf(ws, r3, acc3);
        }

        float4 o; o.x = acc0; o.y = acc1; o.z = acc2; o.w = acc3;
        ((float4*)out)[g] = o;
    } else {
        // Tail path (unused for B divisible by 4, kept for generality)
        for (long long i = base; i < B && i < base + 4; i++) {
            float xv[M_DIM];
            #pragma unroll
            for (int m = 0; m < M_DIM; m++) xv[m] = x[3 * i + m];
            float acc = 0.0f;
            #pragma unroll
            for (int s = 0; s < NSEG; s++) {
                float r = 0.0f;
                #pragma unroll
                for (int m = 0; m < M_DIM; m++) {
                    const int l = s - 3 * m;
                    if (l < 0 || l >= L_DIM) continue;
                    float lo, hi; upk2(sP[m * L_DIM + l], lo, hi);
                    float d = xv[m] + lo;
                    float u = d * d;
                    float v = fmaf(fmaf(fmaf(u, C3_COEF, C2_COEF), u, C1_COEF), u, 1.0f);
                    bool cc = (d > niv[m]) && (d <= piv[m]);
                    r = cc ? v : r;
                }
                acc = fmaf(sW[s], r, acc);
            }
            out[i] = acc;
        }
    }

    if (base < M_DIM * L_DIM) {
        #pragma unroll
        for (int k = 0; k < 4; k++)
            if (base + k < M_DIM * L_DIM) out[B + base + k] = w[base + k];
    }
}

extern "C" void kernel_launch(void* const* d_in, const int* in_sizes, int n_in,
                              void* d_out, int out_size) {
    const float* x        = (const float*)d_in[0];   // (B, 3)
    const float* phis     = (const float*)d_in[1];   // (3, 16)
    const float* interval = (const float*)d_in[2];   // (3,)
    const float* weight   = (const float*)d_in[3];   // (48,)
    float* out = (float*)d_out;

    int B = in_sizes[0] / M_DIM;

    setup_kernel<<<1, 64>>>(phis, interval);
    int threads = 256;
    long long nthreads = ((long long)B + 3) / 4;
    int blocks = (int)((nthreads + threads - 1) / threads);
    main_kernel<<<blocks, threads>>>(x, weight, out, B);
}

// round 3
// speedup vs baseline: 1.0569x; 1.0569x over previous
#include <cuda_runtime.h>
#include <cuda_bf16.h>

// Problem: M=3, L=16, BATCH=2e6.
// y[b] = sum_{s=0}^{21} w[s] * r_s, r_s = value of largest-m valid candidate
// (l = s-3m in [0,15]) with cond true; val = 0.5*cos(x_m - phi_{m,l}) + 0.5.
// cond = (d > -iv_m) && (d <= iv_m), d = x_m - phi_{m,l}  (computed EXACTLY as ref).
// val via degree-6 even Taylor of 0.5+0.5cos(d) on |d|<=1 (max abs err 1.22e-5).
// Output: d_out[0..B) = y, d_out[B..B+48) = weight echo.
//
// R3 change: __launch_bounds__(256, 4) caps regs at 64 (R2 used 118 -> occ 22.5%).

#define M_DIM 3
#define L_DIM 16
#define NSEG 22

typedef unsigned long long u64p;  // packed f32x2 carrier

__device__ __forceinline__ u64p pk2(float lo, float hi) {
    u64p r; asm("mov.b64 %0, {%1, %2};" : "=l"(r) : "f"(lo), "f"(hi)); return r;
}
__device__ __forceinline__ void upk2(u64p v, float& lo, float& hi) {
    asm("mov.b64 {%0, %1}, %2;" : "=f"(lo), "=f"(hi) : "l"(v));
}
__device__ __forceinline__ u64p add2(u64p a, u64p b) {
    u64p r; asm("add.rn.f32x2 %0, %1, %2;" : "=l"(r) : "l"(a), "l"(b)); return r;
}
__device__ __forceinline__ u64p mul2(u64p a, u64p b) {
    u64p r; asm("mul.rn.f32x2 %0, %1, %2;" : "=l"(r) : "l"(a), "l"(b)); return r;
}
__device__ __forceinline__ u64p fma2(u64p a, u64p b, u64p c) {
    u64p r; asm("fma.rn.f32x2 %0, %1, %2, %3;" : "=l"(r) : "l"(a), "l"(b), "l"(c)); return r;
}

// Precomputed: duplicated (-phi,-phi) per entry; per-m interval bounds.
__device__ u64p  g_nphi2[M_DIM * L_DIM];
__device__ float g_niv[M_DIM];
__device__ float g_piv[M_DIM];

__global__ void setup_kernel(const float* __restrict__ phis,
                             const float* __restrict__ interval) {
    int e = threadIdx.x;
    if (e < M_DIM * L_DIM) {
        float np = -phis[e];
        g_nphi2[e] = pk2(np, np);
    }
    if (e < M_DIM) {
        float iv = interval[e];
        g_niv[e] = -iv;
        g_piv[e] = iv;
    }
}

// Taylor of 0.5 + 0.5*cos(d) in u = d*d
#define C1_COEF (-0.25f)
#define C2_COEF (2.0833333333e-2f)   //  1/48
#define C3_COEF (-6.9444444444e-4f)  // -1/1440

__global__ void __launch_bounds__(256, 4)
main_kernel(const float* __restrict__ x,
            const float* __restrict__ w,
            float* __restrict__ out,
            int B) {
    __shared__ u64p  sP[M_DIM * L_DIM];
    __shared__ float sW[NSEG];
    __shared__ float sNiv[M_DIM];
    __shared__ float sPiv[M_DIM];

    int t = threadIdx.x;
    if (t < M_DIM * L_DIM) sP[t] = g_nphi2[t];
    if (t < NSEG)          sW[t] = w[t];
    if (t < M_DIM) { sNiv[t] = g_niv[t]; sPiv[t] = g_piv[t]; }
    __syncthreads();

    long long g = (long long)blockIdx.x * blockDim.x + t;
    long long base = 4 * g;
    if (base >= B) return;

    float niv[M_DIM], piv[M_DIM];
    #pragma unroll
    for (int m = 0; m < M_DIM; m++) { niv[m] = sNiv[m]; piv[m] = sPiv[m]; }

    const u64p C1p  = pk2(C1_COEF, C1_COEF);
    const u64p C2p  = pk2(C2_COEF, C2_COEF);
    const u64p C3p  = pk2(C3_COEF, C3_COEF);
    const u64p ONEp = pk2(1.0f, 1.0f);

    if (base + 3 < B) {
        // 4 elements: 12 consecutive floats = 3 aligned float4s
        const float4* x4 = (const float4*)x;
        float4 a = x4[3 * g + 0];
        float4 b = x4[3 * g + 1];
        float4 c = x4[3 * g + 2];
        // element e, component m lives at float index 3e+m
        u64p xm[M_DIM][2];
        xm[0][0] = pk2(a.x, a.w);  xm[0][1] = pk2(b.z, c.y);
        xm[1][0] = pk2(a.y, b.x);  xm[1][1] = pk2(b.w, c.z);
        xm[2][0] = pk2(a.z, b.y);  xm[2][1] = pk2(c.x, c.w);

        float acc0 = 0.0f, acc1 = 0.0f, acc2 = 0.0f, acc3 = 0.0f;

        #pragma unroll
        for (int s = 0; s < NSEG; s++) {
            float r0 = 0.0f, r1 = 0.0f, r2 = 0.0f, r3 = 0.0f;
            #pragma unroll
            for (int m = 0; m < M_DIM; m++) {
                const int l = s - 3 * m;
                if (l < 0 || l >= L_DIM) continue;
                u64p ph = sP[m * L_DIM + l];
                u64p dA = add2(xm[m][0], ph);            // d = x + (-phi), exact
                u64p dB = add2(xm[m][1], ph);
                u64p uA = mul2(dA, dA);
                u64p uB = mul2(dB, dB);
                u64p tA = fma2(uA, C3p, C2p);
                u64p tB = fma2(uB, C3p, C2p);
                tA = fma2(tA, uA, C1p);
                tB = fma2(tB, uB, C1p);
                u64p vA = fma2(tA, uA, ONEp);
                u64p vB = fma2(tB, uB, ONEp);
                float d0, d1, d2, d3, v0, v1, v2, v3;
                upk2(dA, d0, d1); upk2(dB, d2, d3);
                upk2(vA, v0, v1); upk2(vB, v2, v3);
                // cond computed exactly as reference
                bool c0 = (d0 > niv[m]) && (d0 <= piv[m]);
                bool c1 = (d1 > niv[m]) && (d1 <= piv[m]);
                bool c2 = (d2 > niv[m]) && (d2 <= piv[m]);
                bool c3 = (d3 > niv[m]) && (d3 <= piv[m]);
                r0 = c0 ? v0 : r0;
                r1 = c1 ? v1 : r1;
                r2 = c2 ? v2 : r2;
                r3 = c3 ? v3 : r3;
            }
            float ws = sW[s];
            acc0 = fmaf(ws, r0, acc0);
            acc1 = fmaf(ws, r1, acc1);
            acc2 = fmaf(ws, r2, acc2);
            acc3 = fmaf(ws, r3, acc3);
        }

        float4 o; o.x = acc0; o.y = acc1; o.z = acc2; o.w = acc3;
        ((float4*)out)[g] = o;
    } else {
        // Tail path (B divisible by 4 in practice)
        for (long long i = base; i < B && i < base + 4; i++) {
            float xv[M_DIM];
            #pragma unroll
            for (int m = 0; m < M_DIM; m++) xv[m] = x[3 * i + m];
            float acc = 0.0f;
            #pragma unroll
            for (int s = 0; s < NSEG; s++) {
                float r = 0.0f;
                #pragma unroll
                for (int m = 0; m < M_DIM; m++) {
                    const int l = s - 3 * m;
                    if (l < 0 || l >= L_DIM) continue;
                    float lo, hi; upk2(sP[m * L_DIM + l], lo, hi);
                    float d = xv[m] + lo;
                    float u = d * d;
                    float v = fmaf(fmaf(fmaf(u, C3_COEF, C2_COEF), u, C1_COEF), u, 1.0f);
                    bool cc = (d > niv[m]) && (d <= piv[m]);
                    r = cc ? v : r;
                }
                acc = fmaf(sW[s], r, acc);
            }
            out[i] = acc;
        }
    }

    if (base < M_DIM * L_DIM) {
        #pragma unroll
        for (int k = 0; k < 4; k++)
            if (base + k < M_DIM * L_DIM) out[B + base + k] = w[base + k];
    }
}

extern "C" void kernel_launch(void* const* d_in, const int* in_sizes, int n_in,
                              void* d_out, int out_size) {
    const float* x        = (const float*)d_in[0];   // (B, 3)
    const float* phis     = (const float*)d_in[1];   // (3, 16)
    const float* interval = (const float*)d_in[2];   // (3,)
    const float* weight   = (const float*)d_in[3];   // (48,)
    float* out = (float*)d_out;

    int B = in_sizes[0] / M_DIM;

    setup_kernel<<<1, 64>>>(phis, interval);
    int threads = 256;
    long long nthreads = ((long long)B + 3) / 4;
    int blocks = (int)((nthreads + threads - 1) / threads);
    main_kernel<<<blocks, threads>>>(x, weight, out, B);
}